// round 3
// baseline (speedup 1.0000x reference)
#include <cuda_runtime.h>

// LDE_58961311040249 — R3: fused two-GEMM, f32x2, conflict-free SMEM,
// 2 CTAs/SM (TILE_T=64), single-ish wave.
//   d[b,t,k]  = s[k] * (||x_bt||^2 - 2 x_bt·m_k + ||m_k||^2)
//   w         = softmax_k(d)
//   out[b,k,i]= (sum_t w*x_i)/T - m[i,k]*(sum_t w)/T

#define B_      16
#define T_      2048
#define NIN     128
#define NOUT    64
#define CHUNKS  32
#define TILE_T  (T_ / CHUNKS)   // 64

#define XS_LD   132   // x row stride (floats); GEMM2 reads are row-contiguous
#define MS_LD   128   // m row stride (floats); XOR-swizzled 16B chunks
#define WS2_LD  66    // w2 row stride (u64 pairs)

__device__ float g_partE [B_ * CHUNKS * NOUT * NIN];  // 16.8 MB scratch
__device__ float g_partWS[B_ * CHUNKS * NOUT];

typedef unsigned long long u64;

__device__ __forceinline__ void lds_v2(u64 &p0, u64 &p1, unsigned smem_off) {
    asm volatile("ld.shared.v2.u64 {%0,%1}, [%2];"
                 : "=l"(p0), "=l"(p1) : "r"(smem_off));
}
__device__ __forceinline__ void fma2(u64 &d, u64 a, u64 b) {
    asm("fma.rn.f32x2 %0, %1, %2, %0;" : "+l"(d) : "l"(a), "l"(b));
}
__device__ __forceinline__ u64 pack2(float lo, float hi) {
    u64 d; asm("mov.b64 %0, {%1,%2};" : "=l"(d) : "f"(lo), "f"(hi)); return d;
}
__device__ __forceinline__ float2 unpack2(u64 v) {
    float2 r; asm("mov.b64 {%0,%1}, %2;" : "=f"(r.x), "=f"(r.y) : "l"(v)); return r;
}

__global__ __launch_bounds__(256, 2) void lde_phase1(
    const float* __restrict__ x,
    const float* __restrict__ s,
    const float* __restrict__ m)
{
    extern __shared__ float smf[];
    float* x_s = smf;                                   // 64*132 f  (33792 B)
    float* m_s = x_s + TILE_T * XS_LD;                  // 64*128 f  (32768 B), swizzled
    u64*   w2  = (u64*)(m_s + NOUT * MS_LD);            // 64*66 u64 (33792 B), (w,w)
    float* xn  = (float*)(w2 + TILE_T * WS2_LD);        // 64
    float* mn  = xn + TILE_T;                           // 64
    float* s_s = mn + NOUT;                             // 64

    const int tid = threadIdx.x;
    const int c   = blockIdx.x;
    const int b   = blockIdx.y;
    const float* xg = x + ((size_t)b * T_ + (size_t)c * TILE_T) * NIN;

    // ---- load M, transposed to [k][i], 16B chunks XOR-swizzled by (k>>2)&7 ----
    for (int e = tid; e < NIN * NOUT; e += 256) {
        int i = e >> 6, k = e & 63;                     // m[i,k] at i*64+k
        int cp = (i >> 2) ^ ((((unsigned)k >> 2) & 7u) << 2);
        m_s[k * MS_LD + (cp << 2) + (i & 3)] = m[e];
    }
    // ---- load X tile ----
    for (int e = tid; e < TILE_T * (NIN / 4); e += 256) {
        int r = e >> 5, i4 = e & 31;
        float4 v = reinterpret_cast<const float4*>(xg)[r * (NIN / 4) + i4];
        reinterpret_cast<float4*>(x_s + r * XS_LD)[i4] = v;
    }
    __syncthreads();

    // ---- row norms: 4 threads per row, shuffle-combined ----
    {
        const int r = tid >> 2, q = tid & 3;
        const float4* row = reinterpret_cast<const float4*>(x_s + r * XS_LD) + q * 8;
        float a = 0.f;
        #pragma unroll
        for (int j = 0; j < 8; j++) {
            float4 v = row[j];
            a += v.x * v.x + v.y * v.y + v.z * v.z + v.w * v.w;
        }
        a += __shfl_xor_sync(0xffffffffu, a, 1);
        a += __shfl_xor_sync(0xffffffffu, a, 2);
        if (q == 0) xn[r] = a;
    }
    {
        const int k = tid >> 2, q = tid & 3;
        const unsigned sk = (((unsigned)k >> 2) & 7u) << 2;
        float a = 0.f;
        #pragma unroll
        for (int j = 0; j < 8; j++) {
            int cp = (q * 8 + j) ^ (int)sk;
            float4 v = *reinterpret_cast<const float4*>(m_s + k * MS_LD + cp * 4);
            a += v.x * v.x + v.y * v.y + v.z * v.z + v.w * v.w;
        }
        a += __shfl_xor_sync(0xffffffffu, a, 1);
        a += __shfl_xor_sync(0xffffffffu, a, 2);
        if (q == 0) { mn[k] = a; s_s[k] = s[k]; }
    }
    __syncthreads();

    const unsigned xb   = (unsigned)__cvta_generic_to_shared(x_s);
    const unsigned mb   = (unsigned)__cvta_generic_to_shared(m_s);
    const unsigned wbse = (unsigned)__cvta_generic_to_shared(w2);

    // ======== GEMM1: dot[r][k] = x_r · m_k  (64x64, micro 4x4, f32x2) ========
    const int tx = tid & 15, ty = tid >> 4;            // ty 0..15
    const int r0 = ty * 4, k0 = tx * 4;
    u64 accp[4][4];
    #pragma unroll
    for (int u = 0; u < 4; u++)
        #pragma unroll
        for (int v = 0; v < 4; v++) accp[u][v] = 0ull;

    const unsigned ax = xb + (unsigned)(r0 * XS_LD) * 4u;
    const unsigned sk1 = ((unsigned)tx & 7u) << 2;     // (k>>2)&7 == tx for k=k0..k0+3

    #pragma unroll 2
    for (int kk = 0; kk < NIN; kk += 4) {
        const unsigned cp = ((unsigned)(kk >> 2)) ^ sk1;   // swizzled 16B chunk
        u64 a0[4], a1[4], b0[4], b1[4];
        #pragma unroll
        for (int u = 0; u < 4; u++)
            lds_v2(a0[u], a1[u], ax + (unsigned)(u * XS_LD + kk) * 4u);
        #pragma unroll
        for (int v = 0; v < 4; v++)
            lds_v2(b0[v], b1[v], mb + ((unsigned)((k0 + v) * MS_LD) + cp * 4u) * 4u);
        #pragma unroll
        for (int u = 0; u < 4; u++)
            #pragma unroll
            for (int v = 0; v < 4; v++) {
                fma2(accp[u][v], a0[u], b0[v]);
                fma2(accp[u][v], a1[u], b1[v]);
            }
    }

    // ======== d-transform + softmax over k (16-lane shuffle groups) ========
    #pragma unroll
    for (int u = 0; u < 4; u++) {
        const int r  = r0 + u;
        const float xr = xn[r];
        float dv[4];
        #pragma unroll
        for (int v = 0; v < 4; v++) {
            float2 p = unpack2(accp[u][v]);
            float dot = p.x + p.y;
            dv[v] = s_s[k0 + v] * (xr - 2.f * dot + mn[k0 + v]);
        }
        float mx = fmaxf(fmaxf(dv[0], dv[1]), fmaxf(dv[2], dv[3]));
        #pragma unroll
        for (int off = 1; off < 16; off <<= 1)
            mx = fmaxf(mx, __shfl_xor_sync(0xffffffffu, mx, off));

        float ev[4], ssum = 0.f;
        #pragma unroll
        for (int v = 0; v < 4; v++) { ev[v] = __expf(dv[v] - mx); ssum += ev[v]; }
        #pragma unroll
        for (int off = 1; off < 16; off <<= 1)
            ssum += __shfl_xor_sync(0xffffffffu, ssum, off);

        const float inv = 1.f / ssum;
        #pragma unroll
        for (int v = 0; v < 4; v++) {
            float wv = ev[v] * inv;
            w2[r * WS2_LD + k0 + v] = pack2(wv, wv);   // pre-duplicated pair
        }
    }
    __syncthreads();

    // ==== GEMM2: E[k][i] = sum_r w[r][k]*x[r][i] (64x128, 4k x (4+4)i, f32x2) ====
    // thread covers i in {4ix..4ix+3} and {64+4ix..64+4ix+3}: lanes contiguous.
    const int ix = tid & 15, ky = tid >> 4;
    const int i0 = ix * 4, kb = ky * 4;
    u64 acc2p[4][4];
    #pragma unroll
    for (int kv = 0; kv < 4; kv++)
        #pragma unroll
        for (int j = 0; j < 4; j++) acc2p[kv][j] = 0ull;

    const unsigned wadr = wbse + (unsigned)kb * 8u;
    const unsigned xadr = xb + (unsigned)i0 * 4u;

    #pragma unroll 4
    for (int r = 0; r < TILE_T; r++) {
        u64 wp[4], xp[4];
        lds_v2(wp[0], wp[1], wadr + (unsigned)(r * WS2_LD) * 8u);
        lds_v2(wp[2], wp[3], wadr + (unsigned)(r * WS2_LD) * 8u + 16u);
        lds_v2(xp[0], xp[1], xadr + (unsigned)(r * XS_LD) * 4u);          // i0..i0+3
        lds_v2(xp[2], xp[3], xadr + (unsigned)(r * XS_LD + 64) * 4u);     // 64+i0..
        #pragma unroll
        for (int kv = 0; kv < 4; kv++)
            #pragma unroll
            for (int j = 0; j < 4; j++)
                fma2(acc2p[kv][j], wp[kv], xp[j]);
    }

    float* pe = g_partE + (size_t)(b * CHUNKS + c) * NOUT * NIN;
    #pragma unroll
    for (int kv = 0; kv < 4; kv++) {
        ulonglong2 o0; o0.x = acc2p[kv][0]; o0.y = acc2p[kv][1];
        ulonglong2 o1; o1.x = acc2p[kv][2]; o1.y = acc2p[kv][3];
        *reinterpret_cast<ulonglong2*>(pe + (kb + kv) * NIN + i0)      = o0;
        *reinterpret_cast<ulonglong2*>(pe + (kb + kv) * NIN + 64 + i0) = o1;
    }

    // ---- per-chunk wsum[k] ----
    if (tid < NOUT) {
        const float* wf = (const float*)w2;
        float a = 0.f;
        #pragma unroll 8
        for (int r = 0; r < TILE_T; r++) a += wf[(r * WS2_LD + tid) * 2];
        g_partWS[(b * CHUNKS + c) * NOUT + tid] = a;
    }
}

__global__ __launch_bounds__(128) void lde_phase2(
    const float* __restrict__ m, float* __restrict__ out)
{
    const int g4 = blockIdx.x * 128 + threadIdx.x;   // 32768 float4 slots
    const int b  = g4 >> 11;
    const int k  = (g4 >> 5) & 63;
    const int i0 = (g4 & 31) * 4;

    float4 se = make_float4(0.f, 0.f, 0.f, 0.f);
    float  sw = 0.f;
    #pragma unroll
    for (int c = 0; c < CHUNKS; c++) {
        const float4 v = *reinterpret_cast<const float4*>(
            g_partE + ((size_t)(b * CHUNKS + c) * NOUT + k) * NIN + i0);
        se.x += v.x; se.y += v.y; se.z += v.z; se.w += v.w;
        sw   += g_partWS[(b * CHUNKS + c) * NOUT + k];
    }
    const float inv_t = 1.f / (float)T_;
    float4 o;
    o.x = (se.x - m[(i0 + 0) * NOUT + k] * sw) * inv_t;
    o.y = (se.y - m[(i0 + 1) * NOUT + k] * sw) * inv_t;
    o.z = (se.z - m[(i0 + 2) * NOUT + k] * sw) * inv_t;
    o.w = (se.w - m[(i0 + 3) * NOUT + k] * sw) * inv_t;
    *reinterpret_cast<float4*>(out + ((size_t)b * NOUT + k) * NIN + i0) = o;
}

extern "C" void kernel_launch(void* const* d_in, const int* in_sizes, int n_in,
                              void* d_out, int out_size)
{
    const float* x = nullptr; const float* s = nullptr; const float* m = nullptr;
    for (int i = 0; i < n_in; i++) {
        if      (in_sizes[i] == B_ * T_ * NIN) x = (const float*)d_in[i];
        else if (in_sizes[i] == NOUT)          s = (const float*)d_in[i];
        else if (in_sizes[i] == NIN * NOUT)    m = (const float*)d_in[i];
    }
    float* out = (float*)d_out;

    const int smem_bytes =
        (TILE_T * XS_LD + NOUT * MS_LD) * (int)sizeof(float)
        + TILE_T * WS2_LD * (int)sizeof(u64)
        + (TILE_T + 2 * NOUT) * (int)sizeof(float);   // ~101 KB

    cudaFuncSetAttribute(lde_phase1,
                         cudaFuncAttributeMaxDynamicSharedMemorySize, smem_bytes);

    lde_phase1<<<dim3(CHUNKS, B_), 256, smem_bytes>>>(x, s, m);
    lde_phase2<<<(B_ * NOUT * NIN) / (128 * 4), 128>>>(m, out);
}

// round 4
// speedup vs baseline: 1.2168x; 1.2168x over previous
#include <cuda_runtime.h>

// LDE_58961311040249 — R4: crossbar-aware fused two-GEMM, f32x2 packed along
// the OUTPUT k-dim (operand pairs come contiguous from natural layouts).
//   d[b,t,k]  = s[k] * (||x_bt||^2 - 2 x_bt·m_k + ||m_k||^2)
//   w         = softmax_k(d)
//   out[b,k,i]= (sum_t w*x_i)/T - m[i,k]*(sum_t w)/T

#define B_      16
#define T_      2048
#define NIN     128
#define NOUT    64
#define CHUNKS  16
#define TILE_T  (T_ / CHUNKS)   // 128

#define XS_LD   130   // x row stride (floats): 4-row lane stride == 8 banks
#define MS_LD   64    // m natural [i][k], 16B-aligned rows
#define WS_LD   68    // w row stride (floats), 16B-aligned

__device__ float g_partE [B_ * CHUNKS * NIN * NOUT];  // [b][c][i][k], 8 MB
__device__ float g_partWS[B_ * CHUNKS * NOUT];

typedef unsigned long long u64;

__device__ __forceinline__ void lds_v2u(u64 &p0, u64 &p1, unsigned off) {
    asm volatile("ld.shared.v2.u64 {%0,%1}, [%2];" : "=l"(p0), "=l"(p1) : "r"(off));
}
__device__ __forceinline__ float2 lds_v2f(unsigned off) {
    float2 r;
    asm volatile("ld.shared.v2.f32 {%0,%1}, [%2];" : "=f"(r.x), "=f"(r.y) : "r"(off));
    return r;
}
__device__ __forceinline__ float lds_f(unsigned off) {
    float r; asm volatile("ld.shared.f32 %0, [%1];" : "=f"(r) : "r"(off)); return r;
}
__device__ __forceinline__ void fma2(u64 &d, u64 a, u64 b) {
    asm("fma.rn.f32x2 %0, %1, %2, %0;" : "+l"(d) : "l"(a), "l"(b));
}
__device__ __forceinline__ u64 dup2(float v) {
    u64 d; asm("mov.b64 %0, {%1,%1};" : "=l"(d) : "f"(v)); return d;
}
__device__ __forceinline__ float2 unpack2(u64 v) {
    float2 r; asm("mov.b64 {%0,%1}, %2;" : "=f"(r.x), "=f"(r.y) : "l"(v)); return r;
}

__global__ __launch_bounds__(256) void lde_phase1(
    const float* __restrict__ x,
    const float* __restrict__ s,
    const float* __restrict__ m)
{
    extern __shared__ float smf[];
    float* x_s = smf;                         // 128*130
    float* m_s = x_s + TILE_T * XS_LD;        // 128*64 natural [i][k]
    float* w_s = m_s + NIN * MS_LD;           // 128*68 [r][k]
    float* xn  = w_s + TILE_T * WS_LD;        // 128
    float* mn  = xn + TILE_T;                 // 64
    float* s_s = mn + NOUT;                   // 64

    const int tid = threadIdx.x;
    const int c   = blockIdx.x;
    const int b   = blockIdx.y;
    const float* xg = x + ((size_t)b * T_ + (size_t)c * TILE_T) * NIN;

    // ---- load M natural [i][k]: straight copy, float4, conflict-free ----
    for (int e = tid; e < (NIN * NOUT) / 4; e += 256) {
        float4 v = reinterpret_cast<const float4*>(m)[e];
        reinterpret_cast<float4*>(m_s)[e] = v;   // MS_LD==NOUT: dense
    }
    // ---- load X tile: float4 gmem, 2x v2 stores (XS_LD=130 is 8B-aligned) ----
    for (int e = tid; e < TILE_T * (NIN / 4); e += 256) {
        int r = e >> 5, i4 = (e & 31) * 4;
        float4 v = reinterpret_cast<const float4*>(xg)[e & 31 | 0] ;
        v = reinterpret_cast<const float4*>(xg + r * NIN)[e & 31];
        float* dst = x_s + r * XS_LD + i4;
        *reinterpret_cast<float2*>(dst)     = make_float2(v.x, v.y);
        *reinterpret_cast<float2*>(dst + 2) = make_float2(v.z, v.w);
    }
    __syncthreads();

    const unsigned xb = (unsigned)__cvta_generic_to_shared(x_s);
    const unsigned mb = (unsigned)__cvta_generic_to_shared(m_s);
    const unsigned wb = (unsigned)__cvta_generic_to_shared(w_s);

    // ---- norms, concurrent thread groups, lane-consecutive (conflict-free) ----
    if (tid < 128) {                 // xn[r]: one thread per row, v2 strides
        const unsigned base = xb + (unsigned)(tid * XS_LD) * 4u;
        float a = 0.f;
        #pragma unroll 8
        for (int ii = 0; ii < NIN; ii += 2) {
            float2 v = lds_v2f(base + (unsigned)ii * 4u);
            a += v.x * v.x + v.y * v.y;
        }
        xn[tid] = a;
    } else if (tid < 192) {          // mn[k]: column sums, lanes consecutive k
        const int k = tid - 128;
        float a = 0.f;
        #pragma unroll 8
        for (int i = 0; i < NIN; i++) {
            float v = lds_f(mb + (unsigned)(i * MS_LD + k) * 4u);
            a += v * v;
        }
        mn[k] = a;
    } else {                          // s_s
        s_s[tid - 192] = s[tid - 192];
    }
    __syncthreads();

    // ======== GEMM1: dot[r][k], pairs along k. tile 4r x 8k ========
    const int kb = tid & 7;           // k block: k = 8*kb .. 8*kb+7
    const int rb = tid >> 3;          // r block: r = 4*rb .. 4*rb+3
    const int r0 = rb * 4;
    u64 acc[4][4];                    // [u=row][j=kpair]
    #pragma unroll
    for (int u = 0; u < 4; u++)
        #pragma unroll
        for (int j = 0; j < 4; j++) acc[u][j] = 0ull;

    const unsigned ax = xb + (unsigned)(r0 * XS_LD) * 4u;
    const unsigned bx = mb + (unsigned)(kb * 8) * 4u;

    #pragma unroll 2
    for (int i = 0; i < NIN; i += 2) {
        float2 av[4];
        #pragma unroll
        for (int u = 0; u < 4; u++)
            av[u] = lds_v2f(ax + (unsigned)(u * XS_LD + i) * 4u);
        u64 bp[4], cp[4];
        lds_v2u(bp[0], bp[1], bx + (unsigned)(i * MS_LD) * 4u);
        lds_v2u(bp[2], bp[3], bx + (unsigned)(i * MS_LD) * 4u + 16u);
        lds_v2u(cp[0], cp[1], bx + (unsigned)((i + 1) * MS_LD) * 4u);
        lds_v2u(cp[2], cp[3], bx + (unsigned)((i + 1) * MS_LD) * 4u + 16u);
        u64 a0[4], a1[4];
        #pragma unroll
        for (int u = 0; u < 4; u++) { a0[u] = dup2(av[u].x); a1[u] = dup2(av[u].y); }
        #pragma unroll
        for (int u = 0; u < 4; u++)
            #pragma unroll
            for (int j = 0; j < 4; j++) {
                fma2(acc[u][j], a0[u], bp[j]);
                fma2(acc[u][j], a1[u], cp[j]);
            }
    }

    // ======== softmax over k per row (8 local k + xor-shuffle over kb) ======
    float mnl[8], ssl[8];
    #pragma unroll
    for (int j = 0; j < 4; j++) {
        mnl[2*j]   = mn[kb*8 + 2*j];   mnl[2*j+1] = mn[kb*8 + 2*j + 1];
        ssl[2*j]   = s_s[kb*8 + 2*j];  ssl[2*j+1] = s_s[kb*8 + 2*j + 1];
    }
    #pragma unroll
    for (int u = 0; u < 4; u++) {
        const int r = r0 + u;
        const float xr = xn[r];
        float dv[8];
        #pragma unroll
        for (int j = 0; j < 4; j++) {
            float2 p = unpack2(acc[u][j]);
            dv[2*j]   = ssl[2*j]   * (xr - 2.f * p.x + mnl[2*j]);
            dv[2*j+1] = ssl[2*j+1] * (xr - 2.f * p.y + mnl[2*j+1]);
        }
        float mx = dv[0];
        #pragma unroll
        for (int q = 1; q < 8; q++) mx = fmaxf(mx, dv[q]);
        #pragma unroll
        for (int off = 1; off < 8; off <<= 1)
            mx = fmaxf(mx, __shfl_xor_sync(0xffffffffu, mx, off));

        float ev[8], sum = 0.f;
        #pragma unroll
        for (int q = 0; q < 8; q++) { ev[q] = __expf(dv[q] - mx); sum += ev[q]; }
        #pragma unroll
        for (int off = 1; off < 8; off <<= 1)
            sum += __shfl_xor_sync(0xffffffffu, sum, off);

        const float inv = 1.f / sum;
        float* wr = w_s + r * WS_LD + kb * 8;
        *reinterpret_cast<float4*>(wr)     =
            make_float4(ev[0]*inv, ev[1]*inv, ev[2]*inv, ev[3]*inv);
        *reinterpret_cast<float4*>(wr + 4) =
            make_float4(ev[4]*inv, ev[5]*inv, ev[6]*inv, ev[7]*inv);
    }
    __syncthreads();

    // ======== GEMM2: E[i][k] = sum_r w[r][k]*x[r][i], pairs along k ========
    // thread: kb (4 kpairs = 8 k), ib = tid>>3: i in {ib, ib+32, ib+64, ib+96}
    const int ib = tid >> 3;
    u64 acc2[4][4];                   // [j=kpair][v=i]
    #pragma unroll
    for (int j = 0; j < 4; j++)
        #pragma unroll
        for (int v = 0; v < 4; v++) acc2[j][v] = 0ull;

    const unsigned wx = wb + (unsigned)(kb * 8) * 4u;

    #pragma unroll 4
    for (int r = 0; r < TILE_T; r++) {
        u64 wp[4];
        lds_v2u(wp[0], wp[1], wx + (unsigned)(r * WS_LD) * 4u);
        lds_v2u(wp[2], wp[3], wx + (unsigned)(r * WS_LD) * 4u + 16u);
        u64 xd[4];
        #pragma unroll
        for (int v = 0; v < 4; v++)
            xd[v] = dup2(lds_f(xb + (unsigned)(r * XS_LD + ib + 32 * v) * 4u));
        #pragma unroll
        for (int j = 0; j < 4; j++)
            #pragma unroll
            for (int v = 0; v < 4; v++)
                fma2(acc2[j][v], wp[j], xd[v]);
    }

    // store pairs (k, k+1) contiguous in partE[b][c][i][k]
    float* pe = g_partE + (size_t)(b * CHUNKS + c) * NIN * NOUT;
    #pragma unroll
    for (int v = 0; v < 4; v++) {
        const int i = ib + 32 * v;
        #pragma unroll
        for (int j = 0; j < 4; j++)
            *reinterpret_cast<u64*>(pe + i * NOUT + kb * 8 + 2 * j) = acc2[j][v];
    }

    // ---- per-chunk wsum[k] (lanes consecutive k: conflict-free) ----
    if (tid < NOUT) {
        float a = 0.f;
        #pragma unroll 8
        for (int r = 0; r < TILE_T; r++) a += w_s[r * WS_LD + tid];
        g_partWS[(b * CHUNKS + c) * NOUT + tid] = a;
    }
}

__global__ __launch_bounds__(256) void lde_phase2(
    const float* __restrict__ m, float* __restrict__ out)
{
    const int g  = blockIdx.x * 256 + threadIdx.x;   // 32768 = B*NIN*16
    const int b  = g >> 11;
    const int i  = (g >> 4) & 127;
    const int kq = g & 15;                           // quad of k

    float4 se = make_float4(0.f, 0.f, 0.f, 0.f);
    float4 sw = make_float4(0.f, 0.f, 0.f, 0.f);
    #pragma unroll
    for (int c = 0; c < CHUNKS; c++) {
        const float4 v = *reinterpret_cast<const float4*>(
            g_partE + ((size_t)((b * CHUNKS + c) * NIN + i)) * NOUT + kq * 4);
        se.x += v.x; se.y += v.y; se.z += v.z; se.w += v.w;
        const float4 wv = *reinterpret_cast<const float4*>(
            g_partWS + (b * CHUNKS + c) * NOUT + kq * 4);
        sw.x += wv.x; sw.y += wv.y; sw.z += wv.z; sw.w += wv.w;
    }
    const float4 mv = *reinterpret_cast<const float4*>(m + i * NOUT + kq * 4);
    const float inv_t = 1.f / (float)T_;
    float* ob = out + (size_t)b * NOUT * NIN + i;
    ob[(kq * 4 + 0) * NIN] = (se.x - mv.x * sw.x) * inv_t;
    ob[(kq * 4 + 1) * NIN] = (se.y - mv.y * sw.y) * inv_t;
    ob[(kq * 4 + 2) * NIN] = (se.z - mv.z * sw.z) * inv_t;
    ob[(kq * 4 + 3) * NIN] = (se.w - mv.w * sw.w) * inv_t;
}

extern "C" void kernel_launch(void* const* d_in, const int* in_sizes, int n_in,
                              void* d_out, int out_size)
{
    const float* x = nullptr; const float* s = nullptr; const float* m = nullptr;
    for (int i = 0; i < n_in; i++) {
        if      (in_sizes[i] == B_ * T_ * NIN) x = (const float*)d_in[i];
        else if (in_sizes[i] == NOUT)          s = (const float*)d_in[i];
        else if (in_sizes[i] == NIN * NOUT)    m = (const float*)d_in[i];
    }
    float* out = (float*)d_out;

    const int smem_bytes =
        (TILE_T * XS_LD + NIN * MS_LD + TILE_T * WS_LD + TILE_T + 2 * NOUT)
        * (int)sizeof(float);   // ~135 KB

    cudaFuncSetAttribute(lde_phase1,
                         cudaFuncAttributeMaxDynamicSharedMemorySize, smem_bytes);

    lde_phase1<<<dim3(CHUNKS, B_), 256, smem_bytes>>>(x, s, m);
    lde_phase2<<<(B_ * NIN * 16) / 256, 256>>>(m, out);
}